// round 1
// baseline (speedup 1.0000x reference)
#include <cuda_runtime.h>
#include <cuda_bf16.h>
#include <math.h>

#define Bz   32
#define NMz  131072
#define Pz   256
#define Fz   3
#define Ez   64
#define Hz   4
#define Kz   3
#define DHz  16

#define FINF 3.402823466e+38f

// ---------------- device scratch (static __device__ globals; no allocs) ----
__device__ int   g_idx1[Pz * Kz];
__device__ float g_w1[Pz * Kz];
__device__ float g_part_d[Pz * 32 * Kz];
__device__ int   g_part_i[Pz * 32 * Kz];
__device__ float g_y [Bz * Pz * Fz];
__device__ float g_Q [Bz * Pz * Ez];
__device__ float g_K [Bz * Pz * Ez];
__device__ float g_scores[Bz * Hz * Pz * Pz];   // 33.5 MB, stays in L2
__device__ float g_y2[Bz * Pz * Fz];

// lexicographic top-3 insert (matches lax.top_k tie-breaking: lower index wins)
__device__ __forceinline__ void ins3lex(float d, int i,
    float &d0, int &i0, float &d1, int &i1, float &d2, int &i2) {
  if (d < d2 || (d == d2 && i < i2)) {
    if (d < d1 || (d == d1 && i < i1)) {
      d2 = d1; i2 = i1;
      if (d < d0 || (d == d0 && i < i0)) { d1 = d0; i1 = i0; d0 = d; i0 = i; }
      else                               { d1 = d;  i1 = i; }
    } else { d2 = d; i2 = i; }
  }
}

// ---------------- kernel 1a: knn1 partial (pivots -> mesh) -----------------
// grid (32 chunks, 8 pivot-groups), 256 threads. Chunk of 4096 mesh points in
// shared; warp lanes = 32 pivots of the group (broadcast shared reads), 8 subs.
__global__ void knn1_partial(const float* __restrict__ pos_mesh,
                             const float* __restrict__ pos_piv) {
  __shared__ float2 pts[4096];
  __shared__ float  smd[256 * 3];
  __shared__ int    smi[256 * 3];
  int chunk = blockIdx.x, pg = blockIdx.y;
  int base = chunk * 4096;
  const float2* pm2 = (const float2*)pos_mesh;
  for (int i = threadIdx.x; i < 4096; i += 256) pts[i] = pm2[base + i];
  __syncthreads();

  int pl  = threadIdx.x & 31;
  int sub = threadIdx.x >> 5;
  int p   = pg * 32 + pl;
  float ppx = pos_piv[2 * p], ppy = pos_piv[2 * p + 1];

  float d0 = FINF, d1 = FINF, d2 = FINF;
  int   i0 = -1,  i1 = -1,  i2 = -1;
  int jend = sub * 512 + 512;
  for (int j = sub * 512; j < jend; j++) {
    float2 m = pts[j];
    float dx = ppx - m.x, dy = ppy - m.y;
    float dd = dx * dx + dy * dy;
    if (dd < d2) {           // strict: ascending index => earliest kept on tie
      int gi = base + j;
      if (dd < d1) {
        d2 = d1; i2 = i1;
        if (dd < d0) { d1 = d0; i1 = i0; d0 = dd; i0 = gi; }
        else         { d1 = dd; i1 = gi; }
      } else { d2 = dd; i2 = gi; }
    }
  }
  int t = threadIdx.x;
  smd[t*3+0] = d0; smd[t*3+1] = d1; smd[t*3+2] = d2;
  smi[t*3+0] = i0; smi[t*3+1] = i1; smi[t*3+2] = i2;
  __syncthreads();

  if (t < 32) {  // merge the 8 subs for pivot pl = t
    float b0 = FINF, b1 = FINF, b2 = FINF; int j0 = -1, j1 = -1, j2 = -1;
    for (int s = 0; s < 8; s++) {
      int e = (s * 32 + t) * 3;
      ins3lex(smd[e+0], smi[e+0], b0, j0, b1, j1, b2, j2);
      ins3lex(smd[e+1], smi[e+1], b0, j0, b1, j1, b2, j2);
      ins3lex(smd[e+2], smi[e+2], b0, j0, b1, j1, b2, j2);
    }
    int pp = pg * 32 + t;
    int o = (pp * 32 + chunk) * 3;
    g_part_d[o+0] = b0; g_part_d[o+1] = b1; g_part_d[o+2] = b2;
    g_part_i[o+0] = j0; g_part_i[o+1] = j1; g_part_i[o+2] = j2;
  }
}

// ---------------- kernel 1b: knn1 final merge + weights --------------------
__global__ void knn1_final() {
  int p = threadIdx.x;
  float b0 = FINF, b1 = FINF, b2 = FINF; int j0 = -1, j1 = -1, j2 = -1;
  for (int c = 0; c < 32; c++) {
    int o = (p * 32 + c) * 3;
    ins3lex(g_part_d[o+0], g_part_i[o+0], b0, j0, b1, j1, b2, j2);
    ins3lex(g_part_d[o+1], g_part_i[o+1], b0, j0, b1, j1, b2, j2);
    ins3lex(g_part_d[o+2], g_part_i[o+2], b0, j0, b1, j1, b2, j2);
  }
  float w0 = 1.f / fmaxf(b0, 1e-16f);
  float w1 = 1.f / fmaxf(b1, 1e-16f);
  float w2 = 1.f / fmaxf(b2, 1e-16f);
  float inv = 1.f / (w0 + w1 + w2);
  g_w1[p*3+0] = w0 * inv; g_w1[p*3+1] = w1 * inv; g_w1[p*3+2] = w2 * inv;
  g_idx1[p*3+0] = j0; g_idx1[p*3+1] = j1; g_idx1[p*3+2] = j2;
}

// ---------------- kernel 2: gather + layernorm + weighted interp -----------
// Only the KNN-selected nodes are ever read (sparse gather of node_attr).
__global__ void gather_ln(const float* __restrict__ na,
                          const float* __restrict__ gamma,
                          const float* __restrict__ beta) {
  int b = blockIdx.x, p = threadIdx.x;
  float g0 = gamma[0], g1 = gamma[1], g2 = gamma[2];
  float e0 = beta[0],  e1 = beta[1],  e2 = beta[2];
  float a0 = 0.f, a1 = 0.f, a2 = 0.f;
  #pragma unroll
  for (int k = 0; k < 3; k++) {
    int i = g_idx1[p*3+k];
    float w = g_w1[p*3+k];
    const float* xr = na + ((long)b * NMz + i) * 3;
    float x0 = xr[0], x1 = xr[1], x2 = xr[2];
    float mu = (x0 + x1 + x2) * (1.0f / 3.0f);
    float c0 = x0 - mu, c1 = x1 - mu, c2 = x2 - mu;
    float var = (c0*c0 + c1*c1 + c2*c2) * (1.0f / 3.0f);
    float r = rsqrtf(var + 1e-5f);
    a0 += w * (c0 * r * g0 + e0);
    a1 += w * (c1 * r * g1 + e1);
    a2 += w * (c2 * r * g2 + e2);
  }
  int o = (b * Pz + p) * 3;
  g_y[o+0] = a0; g_y[o+1] = a1; g_y[o+2] = a2;
}

// ---------------- kernel 3: q = Wf y + bf + Wp pos + bp; Q, K projections --
// grid 256 = (b, tile of 32 pivots), 256 threads.
__global__ void proj_kernel(const float* __restrict__ piv,
                            const float* __restrict__ Wf,
                            const float* __restrict__ bf,
                            const float* __restrict__ Wp,
                            const float* __restrict__ bp,
                            const float* __restrict__ inW,
                            const float* __restrict__ inB) {
  __shared__ float q_sh[32 * 64];
  int blk = blockIdx.x;
  int b = blk >> 3, tile = blk & 7;
  int t = threadIdx.x;
  {
    int pl = t >> 3, eg = t & 7;
    int p = tile * 32 + pl;
    int yo = (b * Pz + p) * 3;
    float y0 = g_y[yo], y1 = g_y[yo+1], y2v = g_y[yo+2];
    float px = piv[2*p], py = piv[2*p+1];
    #pragma unroll
    for (int jj = 0; jj < 8; jj++) {
      int e = eg * 8 + jj;
      float v = Wf[e*3+0]*y0 + Wf[e*3+1]*y1 + Wf[e*3+2]*y2v + bf[e]
              + Wp[e*2+0]*px + Wp[e*2+1]*py + bp[e];
      q_sh[pl * 64 + e] = v;
    }
  }
  __syncthreads();
  int pl = t >> 3, oi = t & 7;
  float4 qv[16];
  #pragma unroll
  for (int r = 0; r < 16; r++) qv[r] = *(const float4*)&q_sh[pl * 64 + r * 4];
  int p = tile * 32 + pl;
  long obase = (long)(b * Pz + p) * 64;
  #pragma unroll
  for (int jj = 0; jj < 8; jj++) {
    int eQ = oi * 8 + jj;
    float aq = inB[eQ], ak = inB[64 + eQ];
    const float4* wq = (const float4*)&inW[eQ * 64];
    const float4* wk = (const float4*)&inW[(64 + eQ) * 64];
    #pragma unroll
    for (int r = 0; r < 16; r++) {
      float4 a = wq[r];
      aq += a.x*qv[r].x + a.y*qv[r].y + a.z*qv[r].z + a.w*qv[r].w;
      float4 c = wk[r];
      ak += c.x*qv[r].x + c.y*qv[r].y + c.z*qv[r].z + c.w*qv[r].w;
    }
    g_Q[obase + eQ] = aq;
    g_K[obase + eQ] = ak;
  }
}

// ---------------- kernel 4: scores = Q K^T / 4 per head --------------------
// grid 512 = (b, 16-query tile), 256 threads; 4i x 4j register tile.
__global__ void scores_kernel() {
  extern __shared__ float sm[];
  float* Ksh = sm;              // 256 rows x 65 (padded)
  float* Qsh = sm + 256 * 65;   // 16 rows x 65
  int blk = blockIdx.x;
  int b = blk >> 4, it = blk & 15;
  int i0 = it * 16;
  int t = threadIdx.x;
  const float* Kb = g_K + b * (Pz * Ez);
  for (int idx = t; idx < Pz * Ez; idx += 256)
    Ksh[(idx >> 6) * 65 + (idx & 63)] = Kb[idx];
  const float* Qb = g_Q + b * (Pz * Ez) + i0 * 64;
  for (int idx = t; idx < 16 * 64; idx += 256)
    Qsh[(idx >> 6) * 65 + (idx & 63)] = Qb[idx];
  __syncthreads();

  int tj = t & 63, ig = t >> 6;
  float acc[4][4][4];   // [ir][jl][h]
  #pragma unroll
  for (int a = 0; a < 4; a++)
    #pragma unroll
    for (int c = 0; c < 4; c++)
      #pragma unroll
      for (int h = 0; h < 4; h++) acc[a][c][h] = 0.f;

  #pragma unroll
  for (int h = 0; h < 4; h++) {
    #pragma unroll
    for (int d = 0; d < 16; d++) {
      int e2 = h * 16 + d;
      float q0 = Qsh[(ig*4+0)*65 + e2];
      float q1 = Qsh[(ig*4+1)*65 + e2];
      float q2 = Qsh[(ig*4+2)*65 + e2];
      float q3 = Qsh[(ig*4+3)*65 + e2];
      #pragma unroll
      for (int jl = 0; jl < 4; jl++) {
        float kv = Ksh[(tj + 64*jl)*65 + e2];
        acc[0][jl][h] += q0 * kv;
        acc[1][jl][h] += q1 * kv;
        acc[2][jl][h] += q2 * kv;
        acc[3][jl][h] += q3 * kv;
      }
    }
  }
  #pragma unroll
  for (int ir = 0; ir < 4; ir++) {
    int i = i0 + ig * 4 + ir;
    #pragma unroll
    for (int h = 0; h < 4; h++) {
      long ro = ((long)(b * 4 + h) * 256 + i) * 256;
      #pragma unroll
      for (int jl = 0; jl < 4; jl++)
        g_scores[ro + tj + 64*jl] = acc[ir][jl][h] * 0.25f;
    }
  }
}

// ---------------- kernel 5: per-(b,i) softmax over 4 heads + y2 ------------
__global__ void softmax_y2() {
  int b = blockIdx.x >> 8, i = blockIdx.x & 255;
  int j = threadIdx.x;
  int w = j >> 5, l = j & 31;
  const float* sc = g_scores + ((long)(b * 4) * 256 + i) * 256;
  float s0 = sc[j], s1 = sc[65536 + j], s2 = sc[131072 + j], s3 = sc[196608 + j];

  __shared__ float rd[8][4];
  // block max per head
  float m0 = s0, m1 = s1, m2 = s2, m3 = s3;
  #pragma unroll
  for (int o = 16; o; o >>= 1) {
    m0 = fmaxf(m0, __shfl_xor_sync(0xffffffffu, m0, o));
    m1 = fmaxf(m1, __shfl_xor_sync(0xffffffffu, m1, o));
    m2 = fmaxf(m2, __shfl_xor_sync(0xffffffffu, m2, o));
    m3 = fmaxf(m3, __shfl_xor_sync(0xffffffffu, m3, o));
  }
  if (l == 0) { rd[w][0]=m0; rd[w][1]=m1; rd[w][2]=m2; rd[w][3]=m3; }
  __syncthreads();
  m0 = rd[0][0]; m1 = rd[0][1]; m2 = rd[0][2]; m3 = rd[0][3];
  #pragma unroll
  for (int ww = 1; ww < 8; ww++) {
    m0 = fmaxf(m0, rd[ww][0]); m1 = fmaxf(m1, rd[ww][1]);
    m2 = fmaxf(m2, rd[ww][2]); m3 = fmaxf(m3, rd[ww][3]);
  }
  __syncthreads();

  float e0 = __expf(s0 - m0), e1 = __expf(s1 - m1);
  float e2 = __expf(s2 - m2), e3 = __expf(s3 - m3);
  float t0 = e0, t1 = e1, t2 = e2, t3 = e3;
  #pragma unroll
  for (int o = 16; o; o >>= 1) {
    t0 += __shfl_xor_sync(0xffffffffu, t0, o);
    t1 += __shfl_xor_sync(0xffffffffu, t1, o);
    t2 += __shfl_xor_sync(0xffffffffu, t2, o);
    t3 += __shfl_xor_sync(0xffffffffu, t3, o);
  }
  if (l == 0) { rd[w][0]=t0; rd[w][1]=t1; rd[w][2]=t2; rd[w][3]=t3; }
  __syncthreads();
  float S0=0.f,S1=0.f,S2=0.f,S3=0.f;
  #pragma unroll
  for (int ww = 0; ww < 8; ww++) {
    S0 += rd[ww][0]; S1 += rd[ww][1]; S2 += rd[ww][2]; S3 += rd[ww][3];
  }
  __syncthreads();

  float aw = 0.25f * (__fdividef(e0,S0) + __fdividef(e1,S1)
                    + __fdividef(e2,S2) + __fdividef(e3,S3));
  const float* yb = g_y + (b * Pz + j) * 3;
  float p0 = aw * yb[0], p1 = aw * yb[1], p2 = aw * yb[2];
  #pragma unroll
  for (int o = 16; o; o >>= 1) {
    p0 += __shfl_xor_sync(0xffffffffu, p0, o);
    p1 += __shfl_xor_sync(0xffffffffu, p1, o);
    p2 += __shfl_xor_sync(0xffffffffu, p2, o);
  }
  if (l == 0) { rd[w][0]=p0; rd[w][1]=p1; rd[w][2]=p2; }
  __syncthreads();
  if (j == 0) {
    float r0=0.f,r1=0.f,r2=0.f;
    #pragma unroll
    for (int ww = 0; ww < 8; ww++) { r0+=rd[ww][0]; r1+=rd[ww][1]; r2+=rd[ww][2]; }
    int o = (b * Pz + i) * 3;
    g_y2[o+0]=r0; g_y2[o+1]=r1; g_y2[o+2]=r2;
  }
}

// ---------------- kernel 6: knn2 (mesh->pivots) + interp + 50MB write ------
// grid 512, 256 threads, one mesh point per thread; y2 + pivots in shared.
__global__ void out_kernel(const float* __restrict__ pos_mesh,
                           const float* __restrict__ piv,
                           float* __restrict__ out) {
  extern __shared__ float sh[];
  float*  y2sh = sh;                       // 32*256*3 = 24576 floats
  float2* pv   = (float2*)(sh + 24576);    // 256 float2
  int t = threadIdx.x;
  for (int idx = t; idx < Bz * Pz * Fz; idx += 256) y2sh[idx] = g_y2[idx];
  if (t < 256) pv[t] = ((const float2*)piv)[t];
  __syncthreads();

  int m = blockIdx.x * 256 + t;
  float2 mp = ((const float2*)pos_mesh)[m];
  float d0 = FINF, d1 = FINF, d2 = FINF;
  int   j0 = 0,   j1 = 0,   j2 = 0;
  #pragma unroll 4
  for (int j = 0; j < 256; j++) {
    float2 pp = pv[j];
    float dx = mp.x - pp.x, dy = mp.y - pp.y;
    float dd = dx * dx + dy * dy;
    if (dd < d2) {
      if (dd < d1) {
        d2 = d1; j2 = j1;
        if (dd < d0) { d1 = d0; j1 = j0; d0 = dd; j0 = j; }
        else         { d1 = dd; j1 = j; }
      } else { d2 = dd; j2 = j; }
    }
  }
  float w0 = 1.f / fmaxf(d0, 1e-16f);
  float w1 = 1.f / fmaxf(d1, 1e-16f);
  float w2 = 1.f / fmaxf(d2, 1e-16f);
  float inv = 1.f / (w0 + w1 + w2);
  w0 *= inv; w1 *= inv; w2 *= inv;
  int o0 = j0 * 3, o1 = j1 * 3, o2 = j2 * 3;

  #pragma unroll 4
  for (int b = 0; b < Bz; b++) {
    const float* yb = y2sh + b * (Pz * Fz);
    float r0 = w0*yb[o0+0] + w1*yb[o1+0] + w2*yb[o2+0];
    float r1 = w0*yb[o0+1] + w1*yb[o1+1] + w2*yb[o2+1];
    float r2 = w0*yb[o0+2] + w1*yb[o1+2] + w2*yb[o2+2];
    float* op = out + ((long)b * NMz + m) * 3;
    op[0] = r0; op[1] = r1; op[2] = r2;
  }
}

// ---------------- launch ---------------------------------------------------
extern "C" void kernel_launch(void* const* d_in, const int* in_sizes, int n_in,
                              void* d_out, int out_size) {
  const float* node_attr = (const float*)d_in[0];
  const float* pos_mesh  = (const float*)d_in[1];
  const float* pos_piv   = (const float*)d_in[2];
  const float* gamma     = (const float*)d_in[3];
  const float* beta      = (const float*)d_in[4];
  const float* Wf        = (const float*)d_in[5];
  const float* bf        = (const float*)d_in[6];
  const float* Wp        = (const float*)d_in[7];
  const float* bp        = (const float*)d_in[8];
  const float* inW       = (const float*)d_in[9];
  const float* inB       = (const float*)d_in[10];
  float* out = (float*)d_out;

  const int SMEM_SCORES = (256 * 65 + 16 * 65) * 4;          // 70,720 B
  const int SMEM_OUT    = (Bz * Pz * Fz) * 4 + 256 * 8;      // 100,352 B
  cudaFuncSetAttribute(scores_kernel,
      cudaFuncAttributeMaxDynamicSharedMemorySize, SMEM_SCORES);
  cudaFuncSetAttribute(out_kernel,
      cudaFuncAttributeMaxDynamicSharedMemorySize, SMEM_OUT);

  knn1_partial<<<dim3(32, 8), 256>>>(pos_mesh, pos_piv);
  knn1_final<<<1, 256>>>();
  gather_ln<<<Bz, Pz>>>(node_attr, gamma, beta);
  proj_kernel<<<256, 256>>>(pos_piv, Wf, bf, Wp, bp, inW, inB);
  scores_kernel<<<512, 256, SMEM_SCORES>>>();
  softmax_y2<<<Bz * Pz, 256>>>();
  out_kernel<<<NMz / 256, 256, SMEM_OUT>>>(pos_mesh, pos_piv, out);
}

// round 2
// speedup vs baseline: 1.5844x; 1.5844x over previous
#include <cuda_runtime.h>
#include <cuda_bf16.h>
#include <math.h>

#define Bz   32
#define NMz  131072
#define Pz   256
#define Fz   3
#define Ez   64
#define Hz   4
#define Kz   3
#define DHz  16

#define FINF 3.402823466e+38f

// ---------------- device scratch ----------------
__device__ int   g_idx1[Pz * Kz];
__device__ float g_w1[Pz * Kz];
__device__ float g_part_d[Pz * 32 * Kz];
__device__ int   g_part_i[Pz * 32 * Kz];
__device__ float g_y [Bz * Pz * Fz];
__device__ float g_Q [Bz * Pz * Ez];
__device__ float g_K [Bz * Pz * Ez];
__device__ float g_y2[Bz * Pz * Fz];

__device__ __forceinline__ void ins3lex(float d, int i,
    float &d0, int &i0, float &d1, int &i1, float &d2, int &i2) {
  if (d < d2 || (d == d2 && i < i2)) {
    if (d < d1 || (d == d1 && i < i1)) {
      d2 = d1; i2 = i1;
      if (d < d0 || (d == d0 && i < i0)) { d1 = d0; i1 = i0; d0 = d; i0 = i; }
      else                               { d1 = d;  i1 = i; }
    } else { d2 = d; i2 = i; }
  }
}

// ---------------- kernel 1a: knn1 partial (pivots -> mesh) -----------------
__global__ void knn1_partial(const float* __restrict__ pos_mesh,
                             const float* __restrict__ pos_piv) {
  __shared__ float2 pts[4096];
  __shared__ float  smd[256 * 3];
  __shared__ int    smi[256 * 3];
  int chunk = blockIdx.x, pg = blockIdx.y;
  int base = chunk * 4096;
  const float2* pm2 = (const float2*)pos_mesh;
  for (int i = threadIdx.x; i < 4096; i += 256) pts[i] = pm2[base + i];
  __syncthreads();

  int pl  = threadIdx.x & 31;
  int sub = threadIdx.x >> 5;
  int p   = pg * 32 + pl;
  float ppx = pos_piv[2 * p], ppy = pos_piv[2 * p + 1];

  float d0 = FINF, d1 = FINF, d2 = FINF;
  int   i0 = -1,  i1 = -1,  i2 = -1;
  int jend = sub * 512 + 512;
  for (int j = sub * 512; j < jend; j++) {
    float2 m = pts[j];
    float dx = ppx - m.x, dy = ppy - m.y;
    float dd = dx * dx + dy * dy;
    if (dd < d2) {
      int gi = base + j;
      if (dd < d1) {
        d2 = d1; i2 = i1;
        if (dd < d0) { d1 = d0; i1 = i0; d0 = dd; i0 = gi; }
        else         { d1 = dd; i1 = gi; }
      } else { d2 = dd; i2 = gi; }
    }
  }
  int t = threadIdx.x;
  smd[t*3+0] = d0; smd[t*3+1] = d1; smd[t*3+2] = d2;
  smi[t*3+0] = i0; smi[t*3+1] = i1; smi[t*3+2] = i2;
  __syncthreads();

  if (t < 32) {
    float b0 = FINF, b1 = FINF, b2 = FINF; int j0 = -1, j1 = -1, j2 = -1;
    for (int s = 0; s < 8; s++) {
      int e = (s * 32 + t) * 3;
      ins3lex(smd[e+0], smi[e+0], b0, j0, b1, j1, b2, j2);
      ins3lex(smd[e+1], smi[e+1], b0, j0, b1, j1, b2, j2);
      ins3lex(smd[e+2], smi[e+2], b0, j0, b1, j1, b2, j2);
    }
    int pp = pg * 32 + t;
    int o = (pp * 32 + chunk) * 3;
    g_part_d[o+0] = b0; g_part_d[o+1] = b1; g_part_d[o+2] = b2;
    g_part_i[o+0] = j0; g_part_i[o+1] = j1; g_part_i[o+2] = j2;
  }
}

// ---------------- kernel 1b: knn1 final merge + weights --------------------
__global__ void knn1_final() {
  int p = threadIdx.x;
  float b0 = FINF, b1 = FINF, b2 = FINF; int j0 = -1, j1 = -1, j2 = -1;
  for (int c = 0; c < 32; c++) {
    int o = (p * 32 + c) * 3;
    ins3lex(g_part_d[o+0], g_part_i[o+0], b0, j0, b1, j1, b2, j2);
    ins3lex(g_part_d[o+1], g_part_i[o+1], b0, j0, b1, j1, b2, j2);
    ins3lex(g_part_d[o+2], g_part_i[o+2], b0, j0, b1, j1, b2, j2);
  }
  float w0 = 1.f / fmaxf(b0, 1e-16f);
  float w1 = 1.f / fmaxf(b1, 1e-16f);
  float w2 = 1.f / fmaxf(b2, 1e-16f);
  float inv = 1.f / (w0 + w1 + w2);
  g_w1[p*3+0] = w0 * inv; g_w1[p*3+1] = w1 * inv; g_w1[p*3+2] = w2 * inv;
  g_idx1[p*3+0] = j0; g_idx1[p*3+1] = j1; g_idx1[p*3+2] = j2;
}

// ---------------- kernel 2: gather + layernorm + weighted interp -----------
__global__ void gather_ln(const float* __restrict__ na,
                          const float* __restrict__ gamma,
                          const float* __restrict__ beta) {
  int b = blockIdx.x, p = threadIdx.x;
  float g0 = gamma[0], g1 = gamma[1], g2 = gamma[2];
  float e0 = beta[0],  e1 = beta[1],  e2 = beta[2];
  float a0 = 0.f, a1 = 0.f, a2 = 0.f;
  #pragma unroll
  for (int k = 0; k < 3; k++) {
    int i = g_idx1[p*3+k];
    float w = g_w1[p*3+k];
    const float* xr = na + ((long)b * NMz + i) * 3;
    float x0 = xr[0], x1 = xr[1], x2 = xr[2];
    float mu = (x0 + x1 + x2) * (1.0f / 3.0f);
    float c0 = x0 - mu, c1 = x1 - mu, c2 = x2 - mu;
    float var = (c0*c0 + c1*c1 + c2*c2) * (1.0f / 3.0f);
    float r = rsqrtf(var + 1e-5f);
    a0 += w * (c0 * r * g0 + e0);
    a1 += w * (c1 * r * g1 + e1);
    a2 += w * (c2 * r * g2 + e2);
  }
  int o = (b * Pz + p) * 3;
  g_y[o+0] = a0; g_y[o+1] = a1; g_y[o+2] = a2;
}

// ---------------- kernel 3: q + Q/K projections (shared-staged weights) ----
// grid 256 = (b, tile of 32 pivots), 256 threads.
// Weight reads are warp-uniform (oi = warp id) -> broadcast LDS, no conflicts.
__global__ void __launch_bounds__(256) proj_kernel(
                            const float* __restrict__ piv,
                            const float* __restrict__ Wf,
                            const float* __restrict__ bf,
                            const float* __restrict__ Wp,
                            const float* __restrict__ bp,
                            const float* __restrict__ inW,
                            const float* __restrict__ inB) {
  extern __shared__ float psm[];
  float* Wsh  = psm;               // 128*64 = 8192 (Wq rows 0..63, Wk rows 64..127)
  float* q_sh = Wsh + 8192;        // 32*68 padded
  float* oQ   = q_sh + 32 * 68;    // 32*65 padded
  float* oK   = oQ + 32 * 65;      // 32*65 padded

  int blk = blockIdx.x;
  int b = blk >> 3, tile = blk & 7;
  int t = threadIdx.x;

  for (int idx = t; idx < 8192; idx += 256) Wsh[idx] = inW[idx];
  {
    int pl = t >> 3, eg = t & 7;
    int p = tile * 32 + pl;
    int yo = (b * Pz + p) * 3;
    float y0 = g_y[yo], y1 = g_y[yo+1], y2v = g_y[yo+2];
    float px = piv[2*p], py = piv[2*p+1];
    #pragma unroll
    for (int jj = 0; jj < 8; jj++) {
      int e = eg * 8 + jj;
      float v = Wf[e*3+0]*y0 + Wf[e*3+1]*y1 + Wf[e*3+2]*y2v + bf[e]
              + Wp[e*2+0]*px + Wp[e*2+1]*py + bp[e];
      q_sh[pl * 68 + e] = v;
    }
  }
  __syncthreads();

  int pl = t & 31, oi = t >> 5;           // oi == warp id
  float4 qv[16];
  #pragma unroll
  for (int r = 0; r < 16; r++) qv[r] = *(const float4*)&q_sh[pl * 68 + r * 4];

  #pragma unroll
  for (int jj = 0; jj < 8; jj++) {
    int eQ = oi * 8 + jj;
    float aq = inB[eQ], ak = inB[64 + eQ];
    const float4* wq = (const float4*)&Wsh[eQ * 64];        // warp-uniform
    const float4* wk = (const float4*)&Wsh[(64 + eQ) * 64]; // warp-uniform
    #pragma unroll
    for (int r = 0; r < 16; r++) {
      float4 a = wq[r];
      aq += a.x*qv[r].x + a.y*qv[r].y + a.z*qv[r].z + a.w*qv[r].w;
      float4 c = wk[r];
      ak += c.x*qv[r].x + c.y*qv[r].y + c.z*qv[r].z + c.w*qv[r].w;
    }
    oQ[pl * 65 + eQ] = aq;    // banks (pl+eQ)%32 -> conflict-free
    oK[pl * 65 + eQ] = ak;
  }
  __syncthreads();

  long gb = (long)(b * Pz + tile * 32) * 64;
  for (int idx = t; idx < 2048; idx += 256) {
    int r = idx >> 6, c = idx & 63;
    g_Q[gb + idx] = oQ[r * 65 + c];
    g_K[gb + idx] = oK[r * 65 + c];
  }
}

// ---------------- kernel 4: fused scores + softmax + head-mean + y2 --------
// grid 512 = (b, 16-query tile), 256 threads. No g_scores materialization.
__global__ void __launch_bounds__(256) attn_kernel() {
  extern __shared__ float sm[];
  float* Ksh = sm;                  // 256 x 65
  float* Qsh = Ksh + 256 * 65;      // 16 x 65
  float* ysh = Qsh + 16 * 65;       // 256*3
  float* red = ysh + 768;           // 8 warps x 16
  int blk = blockIdx.x;
  int b = blk >> 4, it = blk & 15;
  int i0 = it * 16;
  int t = threadIdx.x;

  const float* Kb = g_K + b * (Pz * Ez);
  for (int idx = t; idx < Pz * Ez; idx += 256)
    Ksh[(idx >> 6) * 65 + (idx & 63)] = Kb[idx];
  const float* Qb = g_Q + b * (Pz * Ez) + i0 * 64;
  for (int idx = t; idx < 16 * 64; idx += 256)
    Qsh[(idx >> 6) * 65 + (idx & 63)] = Qb[idx];
  for (int idx = t; idx < 768; idx += 256) ysh[idx] = g_y[b * 768 + idx];
  __syncthreads();

  int tj = t & 63, ig = t >> 6;
  int warp = t >> 5;
  float acc[4][4][4];   // [ir][jl][h]
  #pragma unroll
  for (int a = 0; a < 4; a++)
    #pragma unroll
    for (int c = 0; c < 4; c++)
      #pragma unroll
      for (int h = 0; h < 4; h++) acc[a][c][h] = 0.f;

  #pragma unroll
  for (int h = 0; h < 4; h++) {
    #pragma unroll
    for (int d = 0; d < 16; d++) {
      int e2 = h * 16 + d;
      float q0 = Qsh[(ig*4+0)*65 + e2];
      float q1 = Qsh[(ig*4+1)*65 + e2];
      float q2 = Qsh[(ig*4+2)*65 + e2];
      float q3 = Qsh[(ig*4+3)*65 + e2];
      #pragma unroll
      for (int jl = 0; jl < 4; jl++) {
        float kv = Ksh[(tj + 64*jl)*65 + e2];
        acc[0][jl][h] += q0 * kv;
        acc[1][jl][h] += q1 * kv;
        acc[2][jl][h] += q2 * kv;
        acc[3][jl][h] += q3 * kv;
      }
    }
  }
  // scale by 1/sqrt(DH) = 0.25
  #pragma unroll
  for (int a = 0; a < 4; a++)
    #pragma unroll
    for (int c = 0; c < 4; c++)
      #pragma unroll
      for (int h = 0; h < 4; h++) acc[a][c][h] *= 0.25f;

  // ---- softmax max over j (group of 64 threads = warps 2ig, 2ig+1) ----
  float mx[4][4];
  #pragma unroll
  for (int ir = 0; ir < 4; ir++)
    #pragma unroll
    for (int h = 0; h < 4; h++) {
      float m = fmaxf(fmaxf(acc[ir][0][h], acc[ir][1][h]),
                      fmaxf(acc[ir][2][h], acc[ir][3][h]));
      #pragma unroll
      for (int o = 16; o; o >>= 1)
        m = fmaxf(m, __shfl_xor_sync(0xffffffffu, m, o));
      mx[ir][h] = m;
    }
  if ((t & 31) == 0) {
    #pragma unroll
    for (int k = 0; k < 16; k++) red[warp * 16 + k] = mx[k >> 2][k & 3];
  }
  __syncthreads();
  {
    int w0 = (ig * 2) * 16, w1 = (ig * 2 + 1) * 16;
    #pragma unroll
    for (int ir = 0; ir < 4; ir++)
      #pragma unroll
      for (int h = 0; h < 4; h++)
        mx[ir][h] = fmaxf(red[w0 + ir*4 + h], red[w1 + ir*4 + h]);
  }
  __syncthreads();

  // ---- exp + sum ----
  float sv[4][4];
  #pragma unroll
  for (int ir = 0; ir < 4; ir++)
    #pragma unroll
    for (int h = 0; h < 4; h++) {
      float s = 0.f;
      #pragma unroll
      for (int jl = 0; jl < 4; jl++) {
        acc[ir][jl][h] = __expf(acc[ir][jl][h] - mx[ir][h]);
        s += acc[ir][jl][h];
      }
      #pragma unroll
      for (int o = 16; o; o >>= 1)
        s += __shfl_xor_sync(0xffffffffu, s, o);
      sv[ir][h] = s;
    }
  if ((t & 31) == 0) {
    #pragma unroll
    for (int k = 0; k < 16; k++) red[warp * 16 + k] = sv[k >> 2][k & 3];
  }
  __syncthreads();
  {
    int w0 = (ig * 2) * 16, w1 = (ig * 2 + 1) * 16;
    #pragma unroll
    for (int ir = 0; ir < 4; ir++)
      #pragma unroll
      for (int h = 0; h < 4; h++)
        sv[ir][h] = 1.0f / (red[w0 + ir*4 + h] + red[w1 + ir*4 + h]);
  }
  __syncthreads();

  // ---- head-mean attn weight, y2 partial ----
  float p2[4][3];
  #pragma unroll
  for (int ir = 0; ir < 4; ir++) { p2[ir][0]=0.f; p2[ir][1]=0.f; p2[ir][2]=0.f; }
  #pragma unroll
  for (int ir = 0; ir < 4; ir++) {
    #pragma unroll
    for (int jl = 0; jl < 4; jl++) {
      float aw = 0.25f * (acc[ir][jl][0]*sv[ir][0] + acc[ir][jl][1]*sv[ir][1]
                        + acc[ir][jl][2]*sv[ir][2] + acc[ir][jl][3]*sv[ir][3]);
      int j = tj + 64 * jl;
      p2[ir][0] += aw * ysh[j*3+0];
      p2[ir][1] += aw * ysh[j*3+1];
      p2[ir][2] += aw * ysh[j*3+2];
    }
  }
  #pragma unroll
  for (int ir = 0; ir < 4; ir++)
    #pragma unroll
    for (int f = 0; f < 3; f++) {
      float v = p2[ir][f];
      #pragma unroll
      for (int o = 16; o; o >>= 1)
        v += __shfl_xor_sync(0xffffffffu, v, o);
      p2[ir][f] = v;
    }
  if ((t & 31) == 0) {
    #pragma unroll
    for (int ir = 0; ir < 4; ir++)
      #pragma unroll
      for (int f = 0; f < 3; f++) red[warp * 16 + ir*3 + f] = p2[ir][f];
  }
  __syncthreads();
  if (tj == 0) {   // 4 leaders (t = ig*64)
    int w0 = (ig * 2) * 16, w1 = (ig * 2 + 1) * 16;
    #pragma unroll
    for (int ir = 0; ir < 4; ir++) {
      int i = i0 + ig * 4 + ir;
      int o = (b * Pz + i) * 3;
      #pragma unroll
      for (int f = 0; f < 3; f++)
        g_y2[o + f] = red[w0 + ir*3 + f] + red[w1 + ir*3 + f];
    }
  }
}

// ---------------- kernel 6: knn2 (mesh->pivots) + interp + 50MB write ------
__global__ void out_kernel(const float* __restrict__ pos_mesh,
                           const float* __restrict__ piv,
                           float* __restrict__ out) {
  extern __shared__ float sh[];
  float*  y2sh = sh;                       // 32*256*3 floats
  float2* pv   = (float2*)(sh + 24576);    // 256 float2
  int t = threadIdx.x;
  for (int idx = t; idx < Bz * Pz * Fz; idx += 256) y2sh[idx] = g_y2[idx];
  if (t < 256) pv[t] = ((const float2*)piv)[t];
  __syncthreads();

  int m = blockIdx.x * 256 + t;
  float2 mp = ((const float2*)pos_mesh)[m];
  float d0 = FINF, d1 = FINF, d2 = FINF;
  int   j0 = 0,   j1 = 0,   j2 = 0;
  #pragma unroll 4
  for (int j = 0; j < 256; j++) {
    float2 pp = pv[j];
    float dx = mp.x - pp.x, dy = mp.y - pp.y;
    float dd = dx * dx + dy * dy;
    if (dd < d2) {
      if (dd < d1) {
        d2 = d1; j2 = j1;
        if (dd < d0) { d1 = d0; j1 = j0; d0 = dd; j0 = j; }
        else         { d1 = dd; j1 = j; }
      } else { d2 = dd; j2 = j; }
    }
  }
  float w0 = 1.f / fmaxf(d0, 1e-16f);
  float w1 = 1.f / fmaxf(d1, 1e-16f);
  float w2 = 1.f / fmaxf(d2, 1e-16f);
  float inv = 1.f / (w0 + w1 + w2);
  w0 *= inv; w1 *= inv; w2 *= inv;
  int o0 = j0 * 3, o1 = j1 * 3, o2 = j2 * 3;

  #pragma unroll 4
  for (int b = 0; b < Bz; b++) {
    const float* yb = y2sh + b * (Pz * Fz);
    float r0 = w0*yb[o0+0] + w1*yb[o1+0] + w2*yb[o2+0];
    float r1 = w0*yb[o0+1] + w1*yb[o1+1] + w2*yb[o2+1];
    float r2 = w0*yb[o0+2] + w1*yb[o1+2] + w2*yb[o2+2];
    float* op = out + ((long)b * NMz + m) * 3;
    op[0] = r0; op[1] = r1; op[2] = r2;
  }
}

// ---------------- launch ---------------------------------------------------
extern "C" void kernel_launch(void* const* d_in, const int* in_sizes, int n_in,
                              void* d_out, int out_size) {
  const float* node_attr = (const float*)d_in[0];
  const float* pos_mesh  = (const float*)d_in[1];
  const float* pos_piv   = (const float*)d_in[2];
  const float* gamma     = (const float*)d_in[3];
  const float* beta      = (const float*)d_in[4];
  const float* Wf        = (const float*)d_in[5];
  const float* bf        = (const float*)d_in[6];
  const float* Wp        = (const float*)d_in[7];
  const float* bp        = (const float*)d_in[8];
  const float* inW       = (const float*)d_in[9];
  const float* inB       = (const float*)d_in[10];
  float* out = (float*)d_out;

  const int SMEM_PROJ = (8192 + 32*68 + 2 * 32*65) * 4;      // 58,112 B
  const int SMEM_ATTN = (256*65 + 16*65 + 768 + 128) * 4;    // 74,304 B
  const int SMEM_OUT  = (Bz * Pz * Fz) * 4 + 256 * 8;        // 100,352 B
  cudaFuncSetAttribute(proj_kernel,
      cudaFuncAttributeMaxDynamicSharedMemorySize, SMEM_PROJ);
  cudaFuncSetAttribute(attn_kernel,
      cudaFuncAttributeMaxDynamicSharedMemorySize, SMEM_ATTN);
  cudaFuncSetAttribute(out_kernel,
      cudaFuncAttributeMaxDynamicSharedMemorySize, SMEM_OUT);

  knn1_partial<<<dim3(32, 8), 256>>>(pos_mesh, pos_piv);
  knn1_final<<<1, 256>>>();
  gather_ln<<<Bz, Pz>>>(node_attr, gamma, beta);
  proj_kernel<<<256, 256, SMEM_PROJ>>>(pos_piv, Wf, bf, Wp, bp, inW, inB);
  attn_kernel<<<512, 256, SMEM_ATTN>>>();
  out_kernel<<<NMz / 256, 256, SMEM_OUT>>>(pos_mesh, pos_piv, out);
}